// round 3
// baseline (speedup 1.0000x reference)
#include <cuda_runtime.h>
#include <cstdint>
#include <cstddef>

typedef unsigned long long ull;

// Problem constants
#define DD 88
#define HH 256
#define LL 128
#define BB 128
#define TT 1024
#define KIN 344            // DD + HH
#define CSZ 8              // cluster size (CTAs)
#define NCLUST 16
#define NCTA 128
#define NTH 512
#define JQ 86              // K quarter per kh group
#define ZOFF ((size_t)BB * TT * DD)
#define INB_STRIDE_B (KIN * 8 * 4)   // bytes per inbuf buffer = 11008

// SMEM layout (float offsets)
#define WG_OFF    0                       // [32 hid][345 pad][4 gates] = 44160
#define IN_OFF    44160                   // inbuf[2][344][8] = 5504
#define RED_OFF   49664                   // 3 groups x 4 x 128 ull = 3072 floats
#define WOUTS_OFF 52736                   // [32 k][88 d] = 2816
#define UN_OFF    55552                   // union: zbuf[128][8] | hloc[32][8]+ppart[8][88]
#define BGE_OFF   56576                   // [32][4]
#define BGD_OFF   56704
#define BOUTS_OFF 56832                   // 88
#define SMEM_FLOATS 56928
#define SMEM_BYTES (SMEM_FLOATS * 4)      // 227712 B

static_assert(SMEM_BYTES <= 232448, "smem too big");

// x retransposed: g_x2[t][cluster][d][8]
__device__ float g_x2[(size_t)TT * NCLUST * DD * 8];

// ---------------------------------------------------------------------------
__global__ void lstm_init_kernel(const float* __restrict__ x) {
    const int t = blockIdx.x;
    const int b = threadIdx.x;
    #pragma unroll 8
    for (int d = 0; d < DD; d++) {
        g_x2[((size_t)t * NCLUST + (b >> 3)) * (DD * 8) + d * 8 + (b & 7)] =
            x[((size_t)b * TT + t) * DD + d];
    }
}

// ---------------------------------------------------------------------------
__device__ __forceinline__ float sigf(float v) { return 1.0f / (1.0f + expf(-v)); }

__device__ __forceinline__ ull pk2(float x, float y) {
    ull r; asm("mov.b64 %0, {%1, %2};" : "=l"(r) : "f"(x), "f"(y)); return r;
}
__device__ __forceinline__ float2 upk2(ull v) {
    float2 r; asm("mov.b64 {%0, %1}, %2;" : "=f"(r.x), "=f"(r.y) : "l"(v)); return r;
}
#define FMA2(acc, a, b) asm("fma.rn.f32x2 %0, %1, %2, %0;" : "+l"(acc) : "l"(a), "l"(b))

#define CLUSTER_SYNC() do { \
    asm volatile("barrier.cluster.arrive.aligned;" ::: "memory"); \
    asm volatile("barrier.cluster.wait.aligned;" ::: "memory");   \
} while (0)

// map a local smem pointer to rank's DSMEM address (32-bit)
__device__ __forceinline__ uint32_t map_rank(const void* lptr, int rank) {
    uint32_t la = (uint32_t)__cvta_generic_to_shared(lptr), ra;
    asm("mapa.shared::cluster.u32 %0, %1, %2;" : "=r"(ra) : "r"(la), "r"(rank));
    return ra;
}
__device__ __forceinline__ void stc64(uint32_t ra, ull v) {
    asm volatile("st.shared::cluster.b64 [%0], %1;" :: "r"(ra), "l"(v) : "memory");
}
__device__ __forceinline__ void stc32(uint32_t ra, float v) {
    asm volatile("st.shared::cluster.b32 [%0], %1;" :: "r"(ra), "r"(__float_as_uint(v)) : "memory");
}

// Stage this CTA's 128 gate rows: layout [hid][j pad345][gate(i,f,g,o)]
__device__ __forceinline__ void stage_w(float* wg, const float* __restrict__ Wih,
                                        const float* __restrict__ Whh,
                                        int RANK, int tid) {
    for (int idx = tid; idx < 32 * KIN; idx += NTH) {
        int h = idx / KIN, j = idx - h * KIN;
        int rowbase = RANK * 32 + h;
        float* d = wg + h * 1380 + j * 4;
        if (j < DD) {
            #pragma unroll
            for (int g = 0; g < 4; g++) d[g] = Wih[((size_t)(g * HH + rowbase)) * DD + j];
        } else {
            int jj = j - DD;
            #pragma unroll
            for (int g = 0; g < 4; g++) d[g] = Whh[((size_t)(g * HH + rowbase)) * HH + jj];
        }
    }
}

// ---------------------------------------------------------------------------
// 16 clusters x 8 CTAs x 512 threads. Cluster = 8 batch columns.
// CTA rank r owns hidden units [r*32, (r+1)*32) and (decoder) batch r.
// Gates: p=tid&3 (batch pair), hid=(tid>>2)&31, kh=tid>>7 (K quarter 0..3).
// ---------------------------------------------------------------------------
__global__ void __launch_bounds__(NTH, 1) __cluster_dims__(CSZ, 1, 1)
lstm_cluster_kernel(
    const float* __restrict__ Wih_e, const float* __restrict__ Whh_e,
    const float* __restrict__ bih_e, const float* __restrict__ bhh_e,
    const float* __restrict__ Wih_d, const float* __restrict__ Whh_d,
    const float* __restrict__ bih_d, const float* __restrict__ bhh_d,
    const float* __restrict__ W_lat, const float* __restrict__ b_lat,
    const float* __restrict__ W_decinit, const float* __restrict__ b_decinit,
    const float* __restrict__ W_out, const float* __restrict__ b_out,
    float* __restrict__ out)
{
    extern __shared__ float sm[];
    float* wg     = sm + WG_OFF;
    float* inb    = sm + IN_OFF;
    ull*   red64  = (ull*)(sm + RED_OFF);          // [3 groups][4][128]
    float* wout_s = sm + WOUTS_OFF;
    float* zbuf   = sm + UN_OFF;                   // phase A
    float* hloc   = sm + UN_OFF;                   // phase B (decoder)
    float* ppart  = sm + UN_OFF + 256;             // phase B (decoder)
    float* bge    = sm + BGE_OFF;
    float* bgd    = sm + BGD_OFF;
    float* bout_s = sm + BOUTS_OFF;

    const int tid = threadIdx.x;
    const int RANK = blockIdx.x & (CSZ - 1);
    const int CLUST = blockIdx.x >> 3;
    const int p = tid & 3;
    const int hid = (tid >> 2) & 31;
    const int kh = tid >> 7;              // 0..3
    const int q = tid & 127;
    const int b0 = 2 * p;
    const int ghid = RANK * 32 + hid;
    const int j0 = kh * JQ;

    // ---- one-time staging ----
    stage_w(wg, Wih_e, Whh_e, RANK, tid);
    if (tid < 128) {
        int h2 = tid >> 2, g = tid & 3;
        int row = g * HH + RANK * 32 + h2;
        bge[tid] = bih_e[row] + bhh_e[row];
        bgd[tid] = bih_d[row] + bhh_d[row];
    }
    for (int idx = tid; idx < 32 * DD; idx += NTH) {   // wout_s[k][d]
        int d8 = idx >> 5, k = idx & 31;
        wout_s[k * DD + d8] = W_out[(size_t)d8 * HH + RANK * 32 + k];
    }
    if (tid < DD) bout_s[tid] = b_out[tid];
    for (int idx = tid; idx < HH * 8; idx += NTH) inb[DD * 8 + idx] = 0.0f;
    if (tid < 176) {
        *(float4*)(inb + tid * 4) =
            *(const float4*)(g_x2 + ((size_t)0 * NCLUST + CLUST) * (DD * 8) + tid * 4);
    }

    // precomputed remote store addresses for the h broadcast (kh==0 threads)
    uint32_t hdst[CSZ];
    {
        const float* l0 = inb + (DD + ghid) * 8 + b0;   // buffer 0 offset
        #pragma unroll
        for (int r = 0; r < CSZ; r++) hdst[r] = map_rank(l0, r);
    }
    CLUSTER_SYNC();

    int cur = 0;
    float c0 = 0.0f, c1 = 0.0f;
    ull a0, a1, a2, a3;
    float h0v, h1v;

#define GATE_STEP(BIAS)                                                        \
    do {                                                                       \
        const float* wrow = wg + hid * 1380;                                   \
        const float* ib = inb + cur * (KIN * 8);                               \
        if (kh == 0) {                                                         \
            float2 bif = *(const float2*)(BIAS + hid * 4);                     \
            float2 bgo = *(const float2*)(BIAS + hid * 4 + 2);                 \
            a0 = pk2(bif.x, bif.y); a1 = pk2(bgo.x, bgo.y);                    \
            a2 = a0; a3 = a1;                                                  \
        } else { a0 = a1 = a2 = a3 = 0ULL; }                                   \
        _Pragma("unroll 4")                                                    \
        for (int j = j0; j < j0 + JQ; j++) {                                   \
            const ulonglong2 w = *(const ulonglong2*)(wrow + j * 4);           \
            const float2 v = *(const float2*)(ib + j * 8 + b0);                \
            ull vx = pk2(v.x, v.x), vy = pk2(v.y, v.y);                        \
            FMA2(a0, w.x, vx); FMA2(a1, w.y, vx);                              \
            FMA2(a2, w.x, vy); FMA2(a3, w.y, vy);                              \
        }                                                                      \
        if (kh != 0) {                                                         \
            ull* rp = red64 + (kh - 1) * 512;                                  \
            rp[q] = a0; rp[128 + q] = a1; rp[256 + q] = a2; rp[384 + q] = a3;  \
        }                                                                      \
        __syncthreads();                                                       \
        if (kh == 0) {                                                         \
            float2 s0 = upk2(a0), s1 = upk2(a1), s2 = upk2(a2), s3 = upk2(a3); \
            _Pragma("unroll")                                                  \
            for (int g = 0; g < 3; g++) {                                      \
                const ull* rp = red64 + g * 512;                               \
                float2 r0 = upk2(rp[q]),       r1 = upk2(rp[128 + q]);         \
                float2 r2 = upk2(rp[256 + q]), r3 = upk2(rp[384 + q]);         \
                s0.x += r0.x; s0.y += r0.y; s1.x += r1.x; s1.y += r1.y;        \
                s2.x += r2.x; s2.y += r2.y; s3.x += r3.x; s3.y += r3.y;        \
            }                                                                  \
            float i0 = sigf(s0.x), f0 = sigf(s0.y);                            \
            float g0 = tanhf(s1.x), o0 = sigf(s1.y);                           \
            float i1 = sigf(s2.x), f1 = sigf(s2.y);                            \
            float g1 = tanhf(s3.x), o1 = sigf(s3.y);                           \
            c0 = f0 * c0 + i0 * g0;  h0v = o0 * tanhf(c0);                     \
            c1 = f1 * c1 + i1 * g1;  h1v = o1 * tanhf(c1);                     \
            ull hv = pk2(h0v, h1v);                                            \
            const uint32_t cofs = (uint32_t)(cur ^ 1) * INB_STRIDE_B;          \
            _Pragma("unroll")                                                  \
            for (int r8 = 0; r8 < CSZ; r8++) stc64(hdst[r8] + cofs, hv);       \
        }                                                                      \
    } while (0)

    // =============== encoder ===============
    #pragma unroll 1
    for (int t = 0; t < TT; t++) {
        float4 xreg;
        const bool havex = (t + 1 < TT) && (tid < 176);
        if (havex)
            xreg = *(const float4*)(g_x2 + ((size_t)(t + 1) * NCLUST + CLUST) * (DD * 8) + tid * 4);
        GATE_STEP(bge);
        if (havex) *(float4*)(inb + (cur ^ 1) * (KIN * 8) + tid * 4) = xreg;
        CLUSTER_SYNC();
        cur ^= 1;
    }

    // =============== latent z ===============
    if (tid < 128) {
        const int li = tid >> 3, b = tid & 7;
        const int l = RANK * 16 + li;
        const float* wl = W_lat + (size_t)l * HH;
        const float* hb = inb + cur * (KIN * 8) + DD * 8 + b;
        float acc = 0.0f;
        #pragma unroll 8
        for (int k = 0; k < HH; k++) acc += wl[k] * hb[k * 8];
        float z = acc + b_lat[l];
        out[ZOFF + ((size_t)(CLUST * 8 + b)) * LL + l] = z;
        const float* dstz = zbuf + l * 8 + b;
        #pragma unroll
        for (int r8 = 0; r8 < CSZ; r8++) stc32(map_rank(dstz, r8), z);
    }
    CLUSTER_SYNC();

    // restage decoder weights
    stage_w(wg, Wih_d, Whh_d, RANK, tid);
    // zero x rows (pred0 = 0) in inbuf[cur^1]
    if (tid < 176) {
        *(float4*)(inb + (cur ^ 1) * (KIN * 8) + tid * 4) = make_float4(0.f, 0.f, 0.f, 0.f);
    }
    // decoder init: h0 = z @ W_decinit^T + b
    if (tid < 128) {
        const int pd = tid & 3, hd = tid >> 2;
        const int gh = RANK * 32 + hd;
        const float* wd = W_decinit + (size_t)gh * LL;
        float acc0 = b_decinit[gh], acc1 = acc0;
        #pragma unroll 8
        for (int k = 0; k < LL; k++) {
            float2 v = *(const float2*)(zbuf + k * 8 + 2 * pd);
            acc0 += wd[k] * v.x;
            acc1 += wd[k] * v.y;
        }
        const float* dsth = inb + (cur ^ 1) * (KIN * 8) + (DD + gh) * 8 + 2 * pd;
        ull hv = pk2(acc0, acc1);
        #pragma unroll
        for (int r8 = 0; r8 < CSZ; r8++) stc64(map_rank(dsth, r8), hv);
    }
    CLUSTER_SYNC();
    cur ^= 1;
    c0 = 0.0f; c1 = 0.0f;

    // precompute decoder remote addresses
    const int pb = tid & 7;          // batch for pred partials
    const int ds = tid >> 3;         // d slot 0..63 (covers ds and ds+64)
    const bool has2 = (ds + 64) < DD;
    uint32_t pp0 = map_rank(ppart + RANK * DD + ds, pb);
    uint32_t pp1 = pp0 + 64 * 4;
    uint32_t xdst[CSZ];
    if (tid < DD) {
        const float* l0x = inb + tid * 8 + RANK;   // buffer 0 offset
        #pragma unroll
        for (int r = 0; r < CSZ; r++) xdst[r] = map_rank(l0x, r);
    }

    // =============== decoder (autoregressive) ===============
    #pragma unroll 1
    for (int t = 0; t < TT; t++) {
        GATE_STEP(bgd);
        if (kh == 0) *(float2*)(hloc + hid * 8 + b0) = make_float2(h0v, h1v);
        __syncthreads();             // hloc ready (CTA-local)
        // pred partials over this CTA's 32 hidden units -> owner rank pb
        {
            float pa0 = 0.f, pa1 = 0.f;
            #pragma unroll 8
            for (int k = 0; k < 32; k++) {
                float hv = hloc[k * 8 + pb];
                pa0 += hv * wout_s[k * DD + ds];
                if (has2) pa1 += hv * wout_s[k * DD + ds + 64];
            }
            stc32(pp0, pa0);
            if (has2) stc32(pp1, pa1);
        }
        CLUSTER_SYNC();              // h exchange + partials visible
        // owner (batch = RANK): reduce, sigmoid, emit + feedback
        if (tid < DD) {
            float s = bout_s[tid];
            #pragma unroll
            for (int src = 0; src < CSZ; src++) s += ppart[src * DD + tid];
            float pr = sigf(s);
            out[(((size_t)(CLUST * 8 + RANK)) * TT + t) * DD + tid] = pr;
            const uint32_t cofs = (uint32_t)(cur ^ 1) * INB_STRIDE_B;
            #pragma unroll
            for (int r8 = 0; r8 < CSZ; r8++) stc32(xdst[r8] + cofs, pr);
        }
        CLUSTER_SYNC();              // pred feedback visible
        cur ^= 1;
    }
#undef GATE_STEP
}

// ---------------------------------------------------------------------------
extern "C" void kernel_launch(void* const* d_in, const int* in_sizes, int n_in,
                              void* d_out, int out_size) {
    const float* x         = (const float*)d_in[0];
    const float* Wih_e     = (const float*)d_in[1];
    const float* Whh_e     = (const float*)d_in[2];
    const float* bih_e     = (const float*)d_in[3];
    const float* bhh_e     = (const float*)d_in[4];
    const float* Wih_d     = (const float*)d_in[5];
    const float* Whh_d     = (const float*)d_in[6];
    const float* bih_d     = (const float*)d_in[7];
    const float* bhh_d     = (const float*)d_in[8];
    const float* W_lat     = (const float*)d_in[9];
    const float* b_lat     = (const float*)d_in[10];
    const float* W_decinit = (const float*)d_in[11];
    const float* b_decinit = (const float*)d_in[12];
    const float* W_out     = (const float*)d_in[13];
    const float* b_out     = (const float*)d_in[14];
    float* out = (float*)d_out;

    cudaFuncSetAttribute(lstm_cluster_kernel,
                         cudaFuncAttributeMaxDynamicSharedMemorySize, SMEM_BYTES);

    lstm_init_kernel<<<TT, 128>>>(x);
    lstm_cluster_kernel<<<NCTA, NTH, SMEM_BYTES>>>(
        Wih_e, Whh_e, bih_e, bhh_e,
        Wih_d, Whh_d, bih_d, bhh_d,
        W_lat, b_lat, W_decinit, b_decinit, W_out, b_out, out);
}

// round 5
// speedup vs baseline: 1.2084x; 1.2084x over previous
#include <cuda_runtime.h>
#include <cstdint>
#include <cstddef>

typedef unsigned long long ull;

// Problem constants
#define DD 88
#define HH 256
#define LL 128
#define BB 128
#define TT 1024
#define KIN 344            // DD + HH
#define CSZ 8
#define NCLUST 16
#define NCTA 128
#define NTH 256
#define ZOFF ((size_t)BB * TT * DD)

// SMEM layout (float offsets)
#define WG_OFF    0                       // [32 hid (stride 1380)][4 gate (stride 344)][344 j]
#define INBT_OFF  44160                   // [2 buf][8 b][344 j] = 5504
#define RED_OFF   49664                   // [4 g][4 kh][32 hid][8 b] = 4096  (zbuf overlays)
#define WOUT_OFF  53760                   // [32 k][88 d] = 2816
#define PPART_OFF 56576                   // [8 src][88 d] = 704
#define HLOC_OFF  57280                   // [32 hid][8 b] = 256
#define BGE_OFF   57536                   // [32][4]
#define BGD_OFF   57664
#define BOUT_OFF  57792                   // 88 (pad 96)
#define SMEM_FLOATS 57888
#define SMEM_BYTES (SMEM_FLOATS * 4)      // 231552

#define INBT_BUF_FL 2752                  // 344*8
#define INBT_BUF_B  11008
#define WROW 1380                         // hid stride (344*4 + 4 pad)

static_assert(SMEM_BYTES <= 232448, "smem too big");

// x restaged: g_x3[t][cluster][b(8)][d(88)]
__device__ float g_x3[(size_t)TT * NCLUST * 8 * DD];

// ---------------------------------------------------------------------------
__global__ void lstm_init_kernel(const float* __restrict__ x) {
    const int t = blockIdx.x;
    const int b = threadIdx.x;   // 128
    float* dst = g_x3 + (((size_t)t * NCLUST + (b >> 3)) * 8 + (b & 7)) * DD;
    const float* src = x + ((size_t)b * TT + t) * DD;
    #pragma unroll 8
    for (int d = 0; d < DD; d++) dst[d] = src[d];
}

// ---------------------------------------------------------------------------
__device__ __forceinline__ float sigfast(float x) {
    return __fdividef(1.0f, 1.0f + __expf(-x));
}
__device__ __forceinline__ float tanhfast(float x) {
    float e = __expf(-2.0f * fabsf(x));
    float t = __fdividef(1.0f - e, 1.0f + e);
    return copysignf(t, x);
}

#define FMA2(acc, a, b) asm("fma.rn.f32x2 %0, %1, %2, %0;" : "+l"(acc) : "l"(a), "l"(b))

#define CLUSTER_SYNC() do { \
    asm volatile("barrier.cluster.arrive.aligned;" ::: "memory"); \
    asm volatile("barrier.cluster.wait.aligned;" ::: "memory");   \
} while (0)

__device__ __forceinline__ uint32_t map_rank(const void* lptr, int rank) {
    uint32_t la = (uint32_t)__cvta_generic_to_shared(lptr), ra;
    asm("mapa.shared::cluster.u32 %0, %1, %2;" : "=r"(ra) : "r"(la), "r"(rank));
    return ra;
}
__device__ __forceinline__ void stc32(uint32_t ra, float v) {
    asm volatile("st.shared::cluster.b32 [%0], %1;" :: "r"(ra), "r"(__float_as_uint(v)) : "memory");
}

// Stage gate weights: wg[hid][gate][j], hid stride WROW, gate stride 344.
__device__ __forceinline__ void stage_w(float* wg, const float* __restrict__ Wih,
                                        const float* __restrict__ Whh,
                                        int RANK, int tid) {
    for (int idx = tid; idx < 32 * 4 * KIN; idx += NTH) {
        int h = idx / (4 * KIN), r = idx - h * (4 * KIN);
        int g = r / KIN, j = r - g * KIN;
        int row = g * HH + RANK * 32 + h;
        wg[h * WROW + g * KIN + j] =
            (j < DD) ? Wih[(size_t)row * DD + j] : Whh[(size_t)row * HH + (j - DD)];
    }
}

// j-paired gate core: acc[g][b] lanes hold (even-j, odd-j) partial sums.
// Both FFMA2 operands come straight from 128-bit shared loads — no splats.
__device__ __forceinline__ void gate_core(const float* __restrict__ wb,
                                          const float* __restrict__ ib,
                                          int j0, int j1, ull acc[4][4]) {
    #pragma unroll 2
    for (int jb = j0; jb < j1; jb += 4) {
        ulonglong2 w0 = *(const ulonglong2*)(wb + 0 * KIN + jb);
        ulonglong2 w1 = *(const ulonglong2*)(wb + 1 * KIN + jb);
        ulonglong2 w2 = *(const ulonglong2*)(wb + 2 * KIN + jb);
        ulonglong2 w3 = *(const ulonglong2*)(wb + 3 * KIN + jb);
        ulonglong2 v0 = *(const ulonglong2*)(ib + 0 * KIN + jb);
        ulonglong2 v1 = *(const ulonglong2*)(ib + 1 * KIN + jb);
        ulonglong2 v2 = *(const ulonglong2*)(ib + 2 * KIN + jb);
        ulonglong2 v3 = *(const ulonglong2*)(ib + 3 * KIN + jb);
        FMA2(acc[0][0], w0.x, v0.x); FMA2(acc[0][0], w0.y, v0.y);
        FMA2(acc[0][1], w0.x, v1.x); FMA2(acc[0][1], w0.y, v1.y);
        FMA2(acc[0][2], w0.x, v2.x); FMA2(acc[0][2], w0.y, v2.y);
        FMA2(acc[0][3], w0.x, v3.x); FMA2(acc[0][3], w0.y, v3.y);
        FMA2(acc[1][0], w1.x, v0.x); FMA2(acc[1][0], w1.y, v0.y);
        FMA2(acc[1][1], w1.x, v1.x); FMA2(acc[1][1], w1.y, v1.y);
        FMA2(acc[1][2], w1.x, v2.x); FMA2(acc[1][2], w1.y, v2.y);
        FMA2(acc[1][3], w1.x, v3.x); FMA2(acc[1][3], w1.y, v3.y);
        FMA2(acc[2][0], w2.x, v0.x); FMA2(acc[2][0], w2.y, v0.y);
        FMA2(acc[2][1], w2.x, v1.x); FMA2(acc[2][1], w2.y, v1.y);
        FMA2(acc[2][2], w2.x, v2.x); FMA2(acc[2][2], w2.y, v2.y);
        FMA2(acc[2][3], w2.x, v3.x); FMA2(acc[2][3], w2.y, v3.y);
        FMA2(acc[3][0], w3.x, v0.x); FMA2(acc[3][0], w3.y, v0.y);
        FMA2(acc[3][1], w3.x, v1.x); FMA2(acc[3][1], w3.y, v1.y);
        FMA2(acc[3][2], w3.x, v2.x); FMA2(acc[3][2], w3.y, v2.y);
        FMA2(acc[3][3], w3.x, v3.x); FMA2(acc[3][3], w3.y, v3.y);
    }
}

// ---------------------------------------------------------------------------
// 16 clusters x 8 CTAs x 256 threads. Cluster = 8 batch columns.
// Gate map: p=tid&1 (4 batches), hid=(tid>>1)&31, kh=tid>>6 (j ranges 88/88/88/80).
// Act map:  ab=tid&7 (batch), ah=tid>>3 (hid) — owns cell state c[ah][ab].
// ---------------------------------------------------------------------------
__global__ void __launch_bounds__(NTH, 1) __cluster_dims__(CSZ, 1, 1)
lstm_cluster_kernel(
    const float* __restrict__ Wih_e, const float* __restrict__ Whh_e,
    const float* __restrict__ bih_e, const float* __restrict__ bhh_e,
    const float* __restrict__ Wih_d, const float* __restrict__ Whh_d,
    const float* __restrict__ bih_d, const float* __restrict__ bhh_d,
    const float* __restrict__ W_lat, const float* __restrict__ b_lat,
    const float* __restrict__ W_decinit, const float* __restrict__ b_decinit,
    const float* __restrict__ W_out, const float* __restrict__ b_out,
    float* __restrict__ out)
{
    extern __shared__ float sm[];
    float* wg     = sm + WG_OFF;
    float* inbT   = sm + INBT_OFF;
    float* red    = sm + RED_OFF;
    float* zbuf   = sm + RED_OFF;     // overlay (disjoint lifetime)
    float* wout_s = sm + WOUT_OFF;
    float* ppart  = sm + PPART_OFF;
    float* hloc   = sm + HLOC_OFF;
    float* bge_s  = sm + BGE_OFF;
    float* bgd_s  = sm + BGD_OFF;
    float* bout_s = sm + BOUT_OFF;

    const int tid = threadIdx.x;
    const int RANK = blockIdx.x & (CSZ - 1);
    const int CLUST = blockIdx.x >> 3;
    const int p = tid & 1;
    const int hid = (tid >> 1) & 31;
    const int kh = tid >> 6;
    const int j0 = kh * 88;
    const int j1 = (kh == 3) ? KIN : j0 + 88;
    const int ab = tid & 7;            // act batch
    const int ah = tid >> 3;           // act hid (0..31)
    const int gha = RANK * 32 + ah;

    // ---- one-time staging ----
    stage_w(wg, Wih_e, Whh_e, RANK, tid);
    if (tid < 128) {
        int h2 = tid >> 2, g = tid & 3;
        int row = g * HH + RANK * 32 + h2;
        bge_s[h2 * 4 + g] = bih_e[row] + bhh_e[row];
        bgd_s[h2 * 4 + g] = bih_d[row] + bhh_d[row];
    }
    for (int idx = tid; idx < 32 * DD; idx += NTH) {
        int d8 = idx >> 5, k = idx & 31;
        wout_s[k * DD + d8] = W_out[(size_t)d8 * HH + RANK * 32 + k];
    }
    if (tid < DD) bout_s[tid] = b_out[tid];
    // inbT buffer 0: h rows zero, x rows = x[0]
    for (int i = tid; i < HH * 8; i += NTH) {
        int b = i >> 8, j = i & 255;
        inbT[b * KIN + DD + j] = 0.0f;
    }
    if (tid < 176) {
        int b = tid / 22, dq = tid % 22;
        *(float4*)(inbT + b * KIN + dq * 4) =
            *(const float4*)(g_x3 + (((size_t)0 * NCLUST + CLUST) * 8 + b) * DD + dq * 4);
    }

    // remote h-store addresses (act threads), buffer 0
    uint32_t hdst[CSZ];
    {
        const float* l0 = inbT + ab * KIN + DD + gha;
        #pragma unroll
        for (int r = 0; r < CSZ; r++) hdst[r] = map_rank(l0, r);
    }
    CLUSTER_SYNC();

    int cur = 0;
    float cst = 0.0f;    // cell state for (gha, ab)
    float hval = 0.0f;

    // One full LSTM step: gate partials -> smem reduce -> activations ->
    // h broadcast to all ranks' inbT[cur^1].
    auto gate_and_act = [&](const float* __restrict__ BIAS) {
        ull acc[4][4];
        #pragma unroll
        for (int g = 0; g < 4; g++)
            #pragma unroll
            for (int b = 0; b < 4; b++) acc[g][b] = 0ULL;
        gate_core(wg + hid * WROW, inbT + cur * INBT_BUF_FL + (4 * p) * KIN,
                  j0, j1, acc);
        #pragma unroll
        for (int g = 0; g < 4; g++) {
            float* rp = red + ((g * 4 + kh) * 32 + hid) * 8 + 4 * p;
            #pragma unroll
            for (int bq = 0; bq < 4; bq += 2) {
                float2 lo = *(float2*)&acc[g][bq];
                float2 hi = *(float2*)&acc[g][bq + 1];
                *(float2*)(rp + bq) = make_float2(lo.x + lo.y, hi.x + hi.y);
            }
        }
        __syncthreads();
        {
            const float* rb = red + ah * 8 + ab;
            float s0 = rb[0*1024] + rb[0*1024+256] + rb[0*1024+512] + rb[0*1024+768];
            float s1 = rb[1*1024] + rb[1*1024+256] + rb[1*1024+512] + rb[1*1024+768];
            float s2 = rb[2*1024] + rb[2*1024+256] + rb[2*1024+512] + rb[2*1024+768];
            float s3 = rb[3*1024] + rb[3*1024+256] + rb[3*1024+512] + rb[3*1024+768];
            s0 += BIAS[ah * 4 + 0]; s1 += BIAS[ah * 4 + 1];
            s2 += BIAS[ah * 4 + 2]; s3 += BIAS[ah * 4 + 3];
            float gi = sigfast(s0), gf = sigfast(s1);
            float gg = tanhfast(s2), go = sigfast(s3);
            cst = gf * cst + gi * gg;
            hval = go * tanhfast(cst);
            const uint32_t cofs = (uint32_t)(cur ^ 1) * INBT_BUF_B;
            #pragma unroll
            for (int r8 = 0; r8 < CSZ; r8++) stc32(hdst[r8] + cofs, hval);
        }
    };

    // =============== encoder ===============
    #pragma unroll 1
    for (int t = 0; t < TT; t++) {
        float4 xreg;
        const bool havex = (t + 1 < TT) && (tid < 176);
        int xb = tid / 22, xdq = tid % 22;
        if (havex)
            xreg = *(const float4*)(g_x3 + (((size_t)(t + 1) * NCLUST + CLUST) * 8 + xb) * DD + xdq * 4);
        gate_and_act(bge_s);
        if (havex)
            *(float4*)(inbT + (cur ^ 1) * INBT_BUF_FL + xb * KIN + xdq * 4) = xreg;
        CLUSTER_SYNC();
        cur ^= 1;
    }

    // =============== latent z ===============
    if (tid < 128) {
        const int li = tid >> 3, zb = tid & 7;
        const int l = RANK * 16 + li;
        const float* wl = W_lat + (size_t)l * HH;
        const float* hb = inbT + cur * INBT_BUF_FL + zb * KIN + DD;
        float a0 = 0.f, a1 = 0.f, a2 = 0.f, a3 = 0.f;
        #pragma unroll 8
        for (int k = 0; k < HH; k += 4) {
            float4 hv = *(const float4*)(hb + k);
            float4 wv = *(const float4*)(wl + k);
            a0 += hv.x * wv.x; a1 += hv.y * wv.y;
            a2 += hv.z * wv.z; a3 += hv.w * wv.w;
        }
        float z = a0 + a1 + a2 + a3 + b_lat[l];
        out[ZOFF + ((size_t)(CLUST * 8 + zb)) * LL + l] = z;
        const float* dstz = zbuf + l * 8 + zb;
        #pragma unroll
        for (int r8 = 0; r8 < CSZ; r8++) stc32(map_rank(dstz, r8), z);
    }
    CLUSTER_SYNC();

    // restage decoder weights; zero x rows of buffer cur^1 (pred0 = 0)
    stage_w(wg, Wih_d, Whh_d, RANK, tid);
    if (tid < 176) {
        int b = tid / 22, dq = tid % 22;
        *(float4*)(inbT + (cur ^ 1) * INBT_BUF_FL + b * KIN + dq * 4) =
            make_float4(0.f, 0.f, 0.f, 0.f);
    }
    // decoder init: h0(gha, ab) = z[:,ab] . W_decinit[gha,:] + b
    {
        const float* wd = W_decinit + (size_t)gha * LL;
        float a0 = b_decinit[gha], a1 = 0.f, a2 = 0.f, a3 = 0.f;
        #pragma unroll 8
        for (int l = 0; l < LL; l += 4) {
            float4 wv = *(const float4*)(wd + l);
            a0 += zbuf[(l + 0) * 8 + ab] * wv.x;
            a1 += zbuf[(l + 1) * 8 + ab] * wv.y;
            a2 += zbuf[(l + 2) * 8 + ab] * wv.z;
            a3 += zbuf[(l + 3) * 8 + ab] * wv.w;
        }
        float h0 = a0 + a1 + a2 + a3;
        const uint32_t cofs = (uint32_t)(cur ^ 1) * INBT_BUF_B;
        #pragma unroll
        for (int r8 = 0; r8 < CSZ; r8++) stc32(hdst[r8] + cofs, h0);
    }
    CLUSTER_SYNC();
    cur ^= 1;
    cst = 0.0f;

    // decoder pred-stage constants
    const int pb = tid & 7;            // batch served
    const int ds = tid >> 3;           // d slot (0..31): d = ds, ds+32, ds+64
    const bool has3 = ds < (DD - 64);
    uint32_t pp0 = map_rank(ppart + RANK * DD + ds, pb);
    uint32_t pp1 = pp0 + 32 * 4;
    uint32_t pp2 = pp0 + 64 * 4;
    uint32_t xdst[CSZ];
    if (tid < DD) {
        const float* l0x = inbT + RANK * KIN + tid;
        #pragma unroll
        for (int r = 0; r < CSZ; r++) xdst[r] = map_rank(l0x, r);
    }

    // =============== decoder (autoregressive) ===============
    #pragma unroll 1
    for (int t = 0; t < TT; t++) {
        gate_and_act(bgd_s);
        hloc[ah * 8 + ab] = hval;
        __syncthreads();
        // pred partials over own 32 hid for batch pb
        {
            float pa0 = 0.f, pa1 = 0.f, pa2 = 0.f;
            #pragma unroll 8
            for (int k = 0; k < 32; k++) {
                float hv = hloc[k * 8 + pb];
                pa0 += hv * wout_s[k * DD + ds];
                pa1 += hv * wout_s[k * DD + ds + 32];
                if (has3) pa2 += hv * wout_s[k * DD + ds + 64];
            }
            stc32(pp0, pa0);
            stc32(pp1, pa1);
            if (has3) stc32(pp2, pa2);
        }
        CLUSTER_SYNC();             // h + partials visible
        if (tid < DD) {
            float s = bout_s[tid];
            #pragma unroll
            for (int src = 0; src < CSZ; src++) s += ppart[src * DD + tid];
            float pr = sigfast(s);
            out[(((size_t)(CLUST * 8 + RANK)) * TT + t) * DD + tid] = pr;
            const uint32_t cofs = (uint32_t)(cur ^ 1) * INBT_BUF_B;
            #pragma unroll
            for (int r8 = 0; r8 < CSZ; r8++) stc32(xdst[r8] + cofs, pr);
        }
        CLUSTER_SYNC();             // pred feedback visible
        cur ^= 1;
    }
}

// ---------------------------------------------------------------------------
extern "C" void kernel_launch(void* const* d_in, const int* in_sizes, int n_in,
                              void* d_out, int out_size) {
    const float* x         = (const float*)d_in[0];
    const float* Wih_e     = (const float*)d_in[1];
    const float* Whh_e     = (const float*)d_in[2];
    const float* bih_e     = (const float*)d_in[3];
    const float* bhh_e     = (const float*)d_in[4];
    const float* Wih_d     = (const float*)d_in[5];
    const float* Whh_d     = (const float*)d_in[6];
    const float* bih_d     = (const float*)d_in[7];
    const float* bhh_d     = (const float*)d_in[8];
    const float* W_lat     = (const float*)d_in[9];
    const float* b_lat     = (const float*)d_in[10];
    const float* W_decinit = (const float*)d_in[11];
    const float* b_decinit = (const float*)d_in[12];
    const float* W_out     = (const float*)d_in[13];
    const float* b_out     = (const float*)d_in[14];
    float* out = (float*)d_out;

    cudaFuncSetAttribute(lstm_cluster_kernel,
                         cudaFuncAttributeMaxDynamicSharedMemorySize, SMEM_BYTES);

    lstm_init_kernel<<<TT, 128>>>(x);
    lstm_cluster_kernel<<<NCTA, NTH, SMEM_BYTES>>>(
        Wih_e, Whh_e, bih_e, bhh_e,
        Wih_d, Whh_d, bih_d, bhh_d,
        W_lat, b_lat, W_decinit, b_decinit, W_out, b_out, out);
}